// round 6
// baseline (speedup 1.0000x reference)
#include <cuda_runtime.h>
#include <cuda_bf16.h>
#include <math.h>

// Quantized softmax (SoftmaxBernoulli2): rows of 2048 int32 in [-128,127].
// LUT[q] = clip(round(exp((q-255)*is)/es),0,255); idx = x - rowmax + 255 (in [0,255]);
// out = LUT[idx] / sum_row(LUT[idx]) as fp32.
//
// R6: 2-row software pipeline — iteration j overlaps max-chain(row j+1) with
// gather+sum+store(row j); ONE barrier per row. Thread-private cp.async staging
// (each thread copies exactly the 32B it reads -> no buffer barriers), depth-3
// ring. Packed 8KB replicated LUT. 6 CTAs/SM.

#define ROW   2048
#define TPB   256
#define NWARP (TPB / 32)
#define NBUF  3

__device__ unsigned g_ptab[64];   // 256-entry exp table packed 4 bytes/word

__global__ void build_table_kernel(const float* __restrict__ input_scale,
                                   const float* __restrict__ exp_scale) {
    int j = threadIdx.x;
    if (j < 64) {
        double is = (double)input_scale[0];
        double es = (double)exp_scale[0];
        unsigned w = 0;
        #pragma unroll
        for (int b = 0; b < 4; b++) {
            int q = 4 * j + b;                      // 0..255 -> quant value q-255
            double r = nearbyint(exp((double)(q - 255) * is) / es);  // half-even
            r = fmin(fmax(r, 0.0), 255.0);
            w |= ((unsigned)(int)r) << (8 * b);
        }
        g_ptab[j] = w;
    }
}

__device__ __forceinline__ void cp_async16(void* smem, const void* gmem) {
    unsigned saddr = (unsigned)__cvta_generic_to_shared(smem);
    asm volatile("cp.async.cg.shared.global [%0], [%1], 16;\n"
                 :: "r"(saddr), "l"(gmem) : "memory");
}
#define CP_COMMIT() asm volatile("cp.async.commit_group;\n" ::: "memory")
#define CP_WAIT1()  asm volatile("cp.async.wait_group 1;\n" ::: "memory")
#define CP_WAIT2()  asm volatile("cp.async.wait_group 2;\n" ::: "memory")

__global__ __launch_bounds__(TPB, 6) void softmax_bernoulli2_kernel(
    const int* __restrict__ x, float* __restrict__ out, int n_rows) {
    __shared__ unsigned s_tab[64 * 32];    // replicated packed LUT, bank == lane
    __shared__ int s_buf[NBUF][ROW];       // staging ring; bytes are thread-private
    __shared__ int s_max[2][NWARP];        // parity-double-buffered partials
    __shared__ int s_sum[2][NWARP];

    const int tid  = threadIdx.x;
    const int lane = tid & 31;
    const int warp = tid >> 5;
    const unsigned laneW = (unsigned)lane;

    #pragma unroll
    for (int i = tid; i < 64 * 32; i += TPB) {
        s_tab[i] = g_ptab[i >> 5];
    }
    // (prologue __syncthreads below fences the LUT fill)

    const long long stride = gridDim.x;    // grid clamped to <= n_rows
    long long row = blockIdx.x;

    // ---- prime the ring: rows row, row+s, row+2s into bufs 0,1,2 ----
    #pragma unroll
    for (int j = 0; j < NBUF; j++) {
        long long rj = row + (long long)j * stride;
        if (rj >= n_rows) rj = row;        // clamped dummy load (data unused)
        const int* g = x + rj * ROW + tid * 4;
        cp_async16(&s_buf[j][tid * 4], g);
        cp_async16(&s_buf[j][1024 + tid * 4], g + 1024);
        CP_COMMIT();
    }

    // ---- prologue: max of first row ----
    CP_WAIT2();                            // own group 0 complete; own bytes visible
    int4 a = *reinterpret_cast<const int4*>(&s_buf[0][tid * 4]);
    int4 b = *reinterpret_cast<const int4*>(&s_buf[0][1024 + tid * 4]);
    int v[8] = {a.x, a.y, a.z, a.w, b.x, b.y, b.z, b.w};
    {
        int m = v[0];
        #pragma unroll
        for (int k = 1; k < 8; k++) m = max(m, v[k]);
        #pragma unroll
        for (int o = 16; o > 0; o >>= 1) m = max(m, __shfl_xor_sync(0xFFFFFFFFu, m, o));
        if (lane == 0) s_max[0][warp] = m;
    }
    __syncthreads();
    int xmax = s_max[0][0];
    #pragma unroll
    for (int w = 1; w < NWARP; w++) xmax = max(xmax, s_max[0][w]);
    int c = 255 - xmax;                    // idx = v + c in [0,255], no clip needed

    int slot = 0;
    int par  = 1;
    for (; row < n_rows; row += stride) {
        int nslot = slot + 1; if (nslot == NBUF) nslot = 0;

        // -- next row: load own bytes (wait_group only, no barrier) + max chain --
        CP_WAIT1();
        int4 na = *reinterpret_cast<const int4*>(&s_buf[nslot][tid * 4]);
        int4 nb = *reinterpret_cast<const int4*>(&s_buf[nslot][1024 + tid * 4]);
        int nm = max(max(max(na.x, na.y), max(na.z, na.w)),
                     max(max(nb.x, nb.y), max(nb.z, nb.w)));
        #pragma unroll
        for (int o = 16; o > 0; o >>= 1) nm = max(nm, __shfl_xor_sync(0xFFFFFFFFu, nm, o));
        if (lane == 0) s_max[par][warp] = nm;

        // -- current row: gather + sum chain (independent of the max chain above) --
        int e[8];
        int sum = 0;
        #pragma unroll
        for (int k = 0; k < 8; k++) {
            unsigned idx = (unsigned)(v[k] + c);
            unsigned w = s_tab[((idx >> 2) << 5) + laneW];
            e[k] = (int)__byte_perm(w, 0, 0x4440u | (idx & 3u));
            sum += e[k];
        }
        #pragma unroll
        for (int o = 16; o > 0; o >>= 1) sum += __shfl_xor_sync(0xFFFFFFFFu, sum, o);
        if (lane == 0) s_sum[par][warp] = sum;

        // -- refill freed slot with row + 3*stride (thread-private bytes) --
        {
            long long pr = row + (long long)NBUF * stride;
            if (pr >= n_rows) pr = row;    // clamped dummy
            const int* g = x + pr * ROW + tid * 4;
            cp_async16(&s_buf[slot][tid * 4], g);
            cp_async16(&s_buf[slot][1024 + tid * 4], g + 1024);
            CP_COMMIT();
        }

        __syncthreads();                   // single barrier: publishes max(next) + sum(cur)

        // -- finish current row: normalize + streaming stores --
        int total = s_sum[par][0];
        #pragma unroll
        for (int w = 1; w < NWARP; w++) total += s_sum[par][w];
        const float inv = 1.0f / (float)total;

        float4 o0, o1;
        o0.x = (float)e[0] * inv; o0.y = (float)e[1] * inv;
        o0.z = (float)e[2] * inv; o0.w = (float)e[3] * inv;
        o1.x = (float)e[4] * inv; o1.y = (float)e[5] * inv;
        o1.z = (float)e[6] * inv; o1.w = (float)e[7] * inv;
        float* ob = out + row * ROW;
        __stcs(reinterpret_cast<float4*>(ob) + tid, o0);
        __stcs(reinterpret_cast<float4*>(ob + 1024) + tid, o1);

        // -- rotate pipeline state --
        int xm = s_max[par][0];
        #pragma unroll
        for (int w = 1; w < NWARP; w++) xm = max(xm, s_max[par][w]);
        c = 255 - xm;
        v[0] = na.x; v[1] = na.y; v[2] = na.z; v[3] = na.w;
        v[4] = nb.x; v[5] = nb.y; v[6] = nb.z; v[7] = nb.w;
        slot = nslot;
        par ^= 1;
    }
}

extern "C" void kernel_launch(void* const* d_in, const int* in_sizes, int n_in,
                              void* d_out, int out_size) {
    const int* x             = (const int*)d_in[0];
    const float* input_scale = (const float*)d_in[1];
    const float* exp_scale   = (const float*)d_in[2];
    float* out = (float*)d_out;

    const int n_rows = in_sizes[0] / ROW;

    int nblocks = 152 * 6;                 // 6 CTAs/SM (32.4KB smem, <=42 regs)
    if (nblocks > n_rows) nblocks = n_rows;

    build_table_kernel<<<1, 64>>>(input_scale, exp_scale);
    softmax_bernoulli2_kernel<<<nblocks, TPB>>>(x, out, n_rows);
}

// round 7
// speedup vs baseline: 1.0418x; 1.0418x over previous
#include <cuda_runtime.h>
#include <cuda_bf16.h>
#include <math.h>

// Quantized softmax (SoftmaxBernoulli2): rows of 2048 int32 in [-128,127].
// LUT[q] = clip(round(exp((q-255)*is)/es),0,255); idx = x - rowmax + 255 (in [0,255]);
// out = LUT[idx] / sum_row(LUT[idx]) as fp32.
//
// R7: warp-per-row. 64 elems/thread packed to bytes (u=v+128), __vmaxu4 max tree +
// shfl, conflict-free packed-LUT gather, e repacked to bytes, shfl sum, float4
// streaming stores. No block barriers, no staging: 32 independent rows in flight
// per SM (4 CTAs x 8 warps), MLP 16 per warp.

#define ROW   2048
#define TPB   256
#define WPC   (TPB / 32)

__device__ unsigned g_ptab[64];   // 256-entry exp table packed 4 bytes/word

__global__ void build_table_kernel(const float* __restrict__ input_scale,
                                   const float* __restrict__ exp_scale) {
    int j = threadIdx.x;
    if (j < 64) {
        double is = (double)input_scale[0];
        double es = (double)exp_scale[0];
        unsigned w = 0;
        #pragma unroll
        for (int b = 0; b < 4; b++) {
            int q = 4 * j + b;                      // 0..255 -> quant value q-255
            double r = nearbyint(exp((double)(q - 255) * is) / es);  // half-even
            r = fmin(fmax(r, 0.0), 255.0);
            w |= ((unsigned)(int)r) << (8 * b);
        }
        g_ptab[j] = w;
    }
}

__device__ __forceinline__ unsigned pack_u(int4 t) {
    // bytes: (t.x+128, t.y+128, t.z+128, t.w+128), each in [0,255]
    unsigned a = __byte_perm((unsigned)(t.x + 128), (unsigned)(t.y + 128), 0x0040);
    unsigned b = __byte_perm((unsigned)(t.z + 128), (unsigned)(t.w + 128), 0x0040);
    return __byte_perm(a, b, 0x5410);
}

__global__ __launch_bounds__(TPB, 4) void softmax_bernoulli2_kernel(
    const int* __restrict__ x, float* __restrict__ out, int n_rows) {
    __shared__ unsigned s_tab[64 * 32];   // replicated packed LUT, bank == lane

    const int tid  = threadIdx.x;
    const int lane = tid & 31;
    const int warp = tid >> 5;

    #pragma unroll
    for (int i = tid; i < 64 * 32; i += TPB) {
        s_tab[i] = g_ptab[i >> 5];
    }
    __syncthreads();                      // only barrier: LUT ready

    long long row = (long long)blockIdx.x * WPC + warp;
    const long long wstride = (long long)gridDim.x * WPC;

    for (; row < n_rows; row += wstride) {
        const int4* xp = reinterpret_cast<const int4*>(x + row * ROW) + lane;

        // ---- load 64 values (16 x LDG.128, batched 8+8) and pack to bytes ----
        unsigned vp[16];
        {
            int4 raw[8];
            #pragma unroll
            for (int k = 0; k < 8; k++) raw[k] = xp[k * 32];
            #pragma unroll
            for (int k = 0; k < 8; k++) vp[k] = pack_u(raw[k]);
            #pragma unroll
            for (int k = 0; k < 8; k++) raw[k] = xp[(k + 8) * 32];
            #pragma unroll
            for (int k = 0; k < 8; k++) vp[k + 8] = pack_u(raw[k]);
        }

        // ---- warp max in packed byte-space ----
        unsigned pm = vp[0];
        #pragma unroll
        for (int k = 1; k < 16; k++) pm = __vmaxu4(pm, vp[k]);
        #pragma unroll
        for (int o = 16; o > 0; o >>= 1)
            pm = __vmaxu4(pm, __shfl_xor_sync(0xFFFFFFFFu, pm, o));
        pm = __vmaxu4(pm, pm >> 16);
        pm = __vmaxu4(pm, pm >> 8);
        const unsigned cu = 255u - (pm & 255u);   // idx = u + cu, in [0,255]

        // ---- gather e from packed LUT, repack e to bytes, accumulate sum ----
        unsigned ep[16];
        int sum = 0;
        #pragma unroll
        for (int k = 0; k < 16; k++) {
            unsigned w = vp[k];
            unsigned i0 = (w & 255u) + cu;
            unsigned i1 = __byte_perm(w, 0, 0x4441u) + cu;
            unsigned i2 = __byte_perm(w, 0, 0x4442u) + cu;
            unsigned i3 = (w >> 24) + cu;
            unsigned e0 = __byte_perm(s_tab[((i0 >> 2) << 5) + lane], 0, 0x4440u | (i0 & 3u));
            unsigned e1 = __byte_perm(s_tab[((i1 >> 2) << 5) + lane], 0, 0x4440u | (i1 & 3u));
            unsigned e2 = __byte_perm(s_tab[((i2 >> 2) << 5) + lane], 0, 0x4440u | (i2 & 3u));
            unsigned e3 = __byte_perm(s_tab[((i3 >> 2) << 5) + lane], 0, 0x4440u | (i3 & 3u));
            sum += (int)(e0 + e1 + e2 + e3);
            ep[k] = e0 | (e1 << 8) | (e2 << 16) | (e3 << 24);
        }

        // ---- warp sum (exact int) ----
        #pragma unroll
        for (int o = 16; o > 0; o >>= 1) sum += __shfl_xor_sync(0xFFFFFFFFu, sum, o);
        const float inv = 1.0f / (float)sum;

        // ---- unpack, normalize, store (16 x STG.128 streaming) ----
        float4* op = reinterpret_cast<float4*>(out + row * ROW) + lane;
        #pragma unroll
        for (int k = 0; k < 16; k++) {
            unsigned w = ep[k];
            float4 o;
            o.x = (float)(w & 255u) * inv;
            o.y = (float)__byte_perm(w, 0, 0x4441u) * inv;
            o.z = (float)__byte_perm(w, 0, 0x4442u) * inv;
            o.w = (float)(w >> 24) * inv;
            __stcs(op + k * 32, o);
        }
    }
}

extern "C" void kernel_launch(void* const* d_in, const int* in_sizes, int n_in,
                              void* d_out, int out_size) {
    const int* x             = (const int*)d_in[0];
    const float* input_scale = (const float*)d_in[1];
    const float* exp_scale   = (const float*)d_in[2];
    float* out = (float*)d_out;

    const int n_rows = in_sizes[0] / ROW;

    int nblocks = 152 * 4;                // 4 CTAs/SM (<=64 regs, 8KB smem)
    int maxb = (n_rows + WPC - 1) / WPC;
    if (nblocks > maxb) nblocks = maxb;

    build_table_kernel<<<1, 64>>>(input_scale, exp_scale);
    softmax_bernoulli2_kernel<<<nblocks, TPB>>>(x, out, n_rows);
}

// round 8
// speedup vs baseline: 1.0744x; 1.0312x over previous
#include <cuda_runtime.h>
#include <cuda_bf16.h>
#include <math.h>

// Quantized softmax (SoftmaxBernoulli2): rows of 2048 int32 in [-128,127].
// LUT[q] = clip(round(exp((q-255)*is)/es),0,255); idx = x - rowmax + 255 (in [0,255]);
// out = LUT[idx] / sum_row(LUT[idx]) as fp32.
//
// R8: single fused kernel (table built per-CTA in the prologue, overlapped with the
// priming cp.async loads) — removes the separate build-table graph node. Body = R5:
// cp.async double-buffered row staging, packed 8KB replicated LUT (conflict-free),
// shfl reductions, streaming stores. 8 CTAs/SM persistent.

#define ROW   2048
#define TPB   256
#define VPT   8
#define NWARP (TPB / 32)

__device__ __forceinline__ void cp_async16(void* smem, const void* gmem) {
    unsigned saddr = (unsigned)__cvta_generic_to_shared(smem);
    asm volatile("cp.async.cg.shared.global [%0], [%1], 16;\n"
                 :: "r"(saddr), "l"(gmem) : "memory");
}
#define CP_COMMIT() asm volatile("cp.async.commit_group;\n" ::: "memory")
#define CP_WAIT1()  asm volatile("cp.async.wait_group 1;\n" ::: "memory")

__global__ __launch_bounds__(TPB, 8) void softmax_bernoulli2_kernel(
    const int* __restrict__ x, float* __restrict__ out,
    const float* __restrict__ input_scale, const float* __restrict__ exp_scale,
    int n_rows) {
    __shared__ unsigned s_tab[64 * 32];   // replicated packed LUT, bank == lane
    __shared__ int s_buf[2][ROW];         // double-buffered staged rows
    __shared__ int s_tmp[256];            // scalar table staging
    __shared__ int s_max[NWARP];
    __shared__ int s_sum[NWARP];

    const int tid  = threadIdx.x;
    const int lane = tid & 31;
    const int warp = tid >> 5;

    const long long stride = gridDim.x;   // grid clamped to <= n_rows
    long long row = blockIdx.x;

    // ---- issue priming loads FIRST so they fly during the table build ----
    {
        const int* s0 = x + row * ROW + tid * 4;
        cp_async16(&s_buf[0][tid * 4], s0);
        cp_async16(&s_buf[0][1024 + tid * 4], s0 + 1024);
        CP_COMMIT();
        long long r1 = row + stride;
        if (r1 >= n_rows) r1 = row;       // clamped dummy
        const int* s1 = x + r1 * ROW + tid * 4;
        cp_async16(&s_buf[1][tid * 4], s1);
        cp_async16(&s_buf[1][1024 + tid * 4], s1 + 1024);
        CP_COMMIT();
    }

    // ---- per-CTA table build: thread tid computes entry tid (double, half-even) ----
    {
        double is = (double)input_scale[0];
        double es = (double)exp_scale[0];
        double r = nearbyint(exp((double)(tid - 255) * is) / es);
        r = fmin(fmax(r, 0.0), 255.0);
        s_tmp[tid] = (int)r;
    }
    __syncthreads();
    // pack 4 entries/word, replicate x32: s_tab[word*32 + lane]
    #pragma unroll
    for (int i = tid; i < 64 * 32; i += TPB) {
        int w4 = (i >> 5) << 2;
        s_tab[i] = (unsigned)s_tmp[w4] | ((unsigned)s_tmp[w4 + 1] << 8) |
                   ((unsigned)s_tmp[w4 + 2] << 16) | ((unsigned)s_tmp[w4 + 3] << 24);
    }
    // (barrier A below fences s_tab before first gather)

    int p = 0;
    for (; row < n_rows; row += stride, p ^= 1) {
        CP_WAIT1();
        __syncthreads();                  // barrier A: buf[p] ready CTA-wide (+ LUT fence)

        int4 a = *reinterpret_cast<const int4*>(&s_buf[p][tid * 8]);
        int4 b = *reinterpret_cast<const int4*>(&s_buf[p][tid * 8 + 4]);
        int v[VPT] = {a.x, a.y, a.z, a.w, b.x, b.y, b.z, b.w};

        // ---- block max ----
        int m = v[0];
        #pragma unroll
        for (int k = 1; k < VPT; k++) m = max(m, v[k]);
        #pragma unroll
        for (int o = 16; o > 0; o >>= 1) m = max(m, __shfl_xor_sync(0xFFFFFFFFu, m, o));
        if (lane == 0) s_max[warp] = m;
        __syncthreads();                  // barrier B: max ready AND buf[p] consumed

        // ---- refill freed buffer with row + 2*stride (clamped) ----
        {
            long long pr = row + 2 * stride;
            if (pr >= n_rows) pr = row;   // clamped dummy
            const int* sp = x + pr * ROW + tid * 4;
            cp_async16(&s_buf[p][tid * 4], sp);
            cp_async16(&s_buf[p][1024 + tid * 4], sp + 1024);
            CP_COMMIT();
        }

        int xmax = s_max[0];
        #pragma unroll
        for (int w = 1; w < NWARP; w++) xmax = max(xmax, s_max[w]);
        const int c = 255 - xmax;         // idx = v + c in [0,255], no clip needed
        const unsigned laneW = (unsigned)lane;

        // ---- gather from packed LUT + exact int sum ----
        int e[VPT];
        int sum = 0;
        #pragma unroll
        for (int k = 0; k < VPT; k++) {
            unsigned idx = (unsigned)(v[k] + c);
            unsigned w = s_tab[((idx >> 2) << 5) + laneW];
            e[k] = (int)__byte_perm(w, 0, 0x4440u | (idx & 3u));
            sum += e[k];
        }
        #pragma unroll
        for (int o = 16; o > 0; o >>= 1) sum += __shfl_xor_sync(0xFFFFFFFFu, sum, o);
        if (lane == 0) s_sum[warp] = sum;
        __syncthreads();                  // barrier C
        int total = s_sum[0];
        #pragma unroll
        for (int w = 1; w < NWARP; w++) total += s_sum[w];

        const float inv = 1.0f / (float)total;

        float4 o0, o1;
        o0.x = (float)e[0] * inv; o0.y = (float)e[1] * inv;
        o0.z = (float)e[2] * inv; o0.w = (float)e[3] * inv;
        o1.x = (float)e[4] * inv; o1.y = (float)e[5] * inv;
        o1.z = (float)e[6] * inv; o1.w = (float)e[7] * inv;
        float4* op = reinterpret_cast<float4*>(out + row * ROW) + tid * 2;
        __stcs(op, o0);                   // streaming stores: no reuse
        __stcs(op + 1, o1);
    }
}

extern "C" void kernel_launch(void* const* d_in, const int* in_sizes, int n_in,
                              void* d_out, int out_size) {
    const int* x             = (const int*)d_in[0];
    const float* input_scale = (const float*)d_in[1];
    const float* exp_scale   = (const float*)d_in[2];
    float* out = (float*)d_out;

    const int n_rows = in_sizes[0] / ROW;

    int nblocks = 152 * 8;                // 8 CTAs/SM (25.6KB smem)
    if (nblocks > n_rows) nblocks = n_rows;

    softmax_bernoulli2_kernel<<<nblocks, TPB>>>(x, out, input_scale, exp_scale, n_rows);
}

// round 9
// speedup vs baseline: 1.0766x; 1.0021x over previous
#include <cuda_runtime.h>
#include <cuda_bf16.h>
#include <math.h>

// Quantized softmax (SoftmaxBernoulli2): rows of 2048 int32 in [-128,127].
// LUT[q] = clip(round(exp((q-255)*is)/es),0,255); idx = x - rowmax + 255 (in [0,255]);
// out = LUT[idx] / sum_row(LUT[idx]) as fp32.
//
// R9: single fused kernel; table built per-CTA via binary-exponentiation
// (1 double exp + <=8 DMUL/thread, ~10x less FP64 than R8's 256 exps/CTA),
// overlapped with priming cp.async. Body = R5: cp.async double-buffered staging,
// packed 8KB replicated LUT (conflict-free), shfl reductions, streaming stores.
// 8 CTAs/SM persistent.

#define ROW   2048
#define TPB   256
#define VPT   8
#define NWARP (TPB / 32)

__device__ __forceinline__ void cp_async16(void* smem, const void* gmem) {
    unsigned saddr = (unsigned)__cvta_generic_to_shared(smem);
    asm volatile("cp.async.cg.shared.global [%0], [%1], 16;\n"
                 :: "r"(saddr), "l"(gmem) : "memory");
}
#define CP_COMMIT() asm volatile("cp.async.commit_group;\n" ::: "memory")
#define CP_WAIT1()  asm volatile("cp.async.wait_group 1;\n" ::: "memory")

__global__ __launch_bounds__(TPB, 8) void softmax_bernoulli2_kernel(
    const int* __restrict__ x, float* __restrict__ out,
    const float* __restrict__ input_scale, const float* __restrict__ exp_scale,
    int n_rows) {
    __shared__ unsigned s_tab[64 * 32];   // replicated packed LUT, bank == lane
    __shared__ int s_buf[2][ROW];         // double-buffered staged rows
    __shared__ int s_tmp[256];            // scalar table staging
    __shared__ double s_r2[8];            // r^(2^j), r = exp(-input_scale)
    __shared__ int s_max[NWARP];
    __shared__ int s_sum[NWARP];

    const int tid  = threadIdx.x;
    const int lane = tid & 31;
    const int warp = tid >> 5;

    const long long stride = gridDim.x;   // grid clamped to <= n_rows
    long long row = blockIdx.x;

    // ---- issue priming loads FIRST so they fly during the table build ----
    {
        const int* s0 = x + row * ROW + tid * 4;
        cp_async16(&s_buf[0][tid * 4], s0);
        cp_async16(&s_buf[0][1024 + tid * 4], s0 + 1024);
        CP_COMMIT();
        long long r1 = row + stride;
        if (r1 >= n_rows) r1 = row;       // clamped dummy
        const int* s1 = x + r1 * ROW + tid * 4;
        cp_async16(&s_buf[1][tid * 4], s1);
        cp_async16(&s_buf[1][1024 + tid * 4], s1 + 1024);
        CP_COMMIT();
    }

    // ---- cheap table build: exp((q-255)*is) = r^(255-q), binary exponentiation ----
    if (tid == 0) {
        double r = exp(-(double)input_scale[0]);  // ONE double exp per CTA
        double p = r;
        #pragma unroll
        for (int j = 0; j < 8; j++) { s_r2[j] = p; p = p * p; }
    }
    __syncthreads();
    {
        double es = (double)exp_scale[0];
        int k = 255 - tid;                // exponent, 0..255
        double t = 1.0;
        #pragma unroll
        for (int j = 0; j < 8; j++) if ((k >> j) & 1) t *= s_r2[j];
        double r = nearbyint(t / es);     // half-even, matches jnp.round
        r = fmin(fmax(r, 0.0), 255.0);
        s_tmp[tid] = (int)r;
    }
    __syncthreads();
    // pack 4 entries/word, replicate x32: s_tab[word*32 + lane]
    #pragma unroll
    for (int i = tid; i < 64 * 32; i += TPB) {
        int w4 = (i >> 5) << 2;
        s_tab[i] = (unsigned)s_tmp[w4] | ((unsigned)s_tmp[w4 + 1] << 8) |
                   ((unsigned)s_tmp[w4 + 2] << 16) | ((unsigned)s_tmp[w4 + 3] << 24);
    }
    // (barrier A below fences s_tab before first gather)

    int p = 0;
    for (; row < n_rows; row += stride, p ^= 1) {
        CP_WAIT1();
        __syncthreads();                  // barrier A: buf[p] ready CTA-wide (+ LUT fence)

        int4 a = *reinterpret_cast<const int4*>(&s_buf[p][tid * 8]);
        int4 b = *reinterpret_cast<const int4*>(&s_buf[p][tid * 8 + 4]);
        int v[VPT] = {a.x, a.y, a.z, a.w, b.x, b.y, b.z, b.w};

        // ---- block max ----
        int m = v[0];
        #pragma unroll
        for (int k = 1; k < VPT; k++) m = max(m, v[k]);
        #pragma unroll
        for (int o = 16; o > 0; o >>= 1) m = max(m, __shfl_xor_sync(0xFFFFFFFFu, m, o));
        if (lane == 0) s_max[warp] = m;
        __syncthreads();                  // barrier B: max ready AND buf[p] consumed

        // ---- refill freed buffer with row + 2*stride (clamped) ----
        {
            long long pr = row + 2 * stride;
            if (pr >= n_rows) pr = row;   // clamped dummy
            const int* sp = x + pr * ROW + tid * 4;
            cp_async16(&s_buf[p][tid * 4], sp);
            cp_async16(&s_buf[p][1024 + tid * 4], sp + 1024);
            CP_COMMIT();
        }

        int xmax = s_max[0];
        #pragma unroll
        for (int w = 1; w < NWARP; w++) xmax = max(xmax, s_max[w]);
        const int c = 255 - xmax;         // idx = v + c in [0,255], no clip needed
        const unsigned laneW = (unsigned)lane;

        // ---- gather from packed LUT + exact int sum ----
        int e[VPT];
        int sum = 0;
        #pragma unroll
        for (int k = 0; k < VPT; k++) {
            unsigned idx = (unsigned)(v[k] + c);
            unsigned w = s_tab[((idx >> 2) << 5) + laneW];
            e[k] = (int)__byte_perm(w, 0, 0x4440u | (idx & 3u));
            sum += e[k];
        }
        #pragma unroll
        for (int o = 16; o > 0; o >>= 1) sum += __shfl_xor_sync(0xFFFFFFFFu, sum, o);
        if (lane == 0) s_sum[warp] = sum;
        __syncthreads();                  // barrier C
        int total = s_sum[0];
        #pragma unroll
        for (int w = 1; w < NWARP; w++) total += s_sum[w];

        const float inv = 1.0f / (float)total;

        float4 o0, o1;
        o0.x = (float)e[0] * inv; o0.y = (float)e[1] * inv;
        o0.z = (float)e[2] * inv; o0.w = (float)e[3] * inv;
        o1.x = (float)e[4] * inv; o1.y = (float)e[5] * inv;
        o1.z = (float)e[6] * inv; o1.w = (float)e[7] * inv;
        float4* op = reinterpret_cast<float4*>(out + row * ROW) + tid * 2;
        __stcs(op, o0);                   // streaming stores: no reuse
        __stcs(op + 1, o1);
    }
}

extern "C" void kernel_launch(void* const* d_in, const int* in_sizes, int n_in,
                              void* d_out, int out_size) {
    const int* x             = (const int*)d_in[0];
    const float* input_scale = (const float*)d_in[1];
    const float* exp_scale   = (const float*)d_in[2];
    float* out = (float*)d_out;

    const int n_rows = in_sizes[0] / ROW;

    int nblocks = 152 * 8;                // 8 CTAs/SM (25.7KB smem)
    if (nblocks > n_rows) nblocks = n_rows;

    softmax_bernoulli2_kernel<<<nblocks, TPB>>>(x, out, input_scale, exp_scale, n_rows);
}